// round 9
// baseline (speedup 1.0000x reference)
#include <cuda_runtime.h>
#include <cuda_fp16.h>
#include <cstdint>

// ============================================================================
// Problem constants
// ============================================================================
#define N_ATOMS   32768
#define N_SPECIES 4
#define N_FEAT    7584
#define HIDDEN    256

#define MT       128        // CTA rows
#define NTILE    128        // CTA cols
#define KC       32         // k-chunk per stage (7584 = 237*32, no padding)
#define NTHREADS 256        // 8 warps, 32x64 warp tiles
#define TOTCH    (N_FEAT / KC)     // 237
#define NCHS     60                // split-K chunks/slice (60,60,60,57)
#define NSPLIT   4

// smem: rows of 32 fp16 = 64B data + 16B pad (stride 80 -> conflict-free ldmatrix)
#define RST      80
#define PLANE    (128 * RST)       // 10240
#define SOFF_AH  0
#define SOFF_AL  (PLANE)
#define SOFF_BH  (2 * PLANE)
#define SOFF_BL  (3 * PLANE)
#define NSTAGE   3

// ============================================================================
// Device scratch (allocation-free)
// ============================================================================
__device__ __align__(16) __half g_W1h[(size_t)N_SPECIES * HIDDEN * N_FEAT];
__device__ __align__(16) __half g_W2h[N_SPECIES * HIDDEN * HIDDEN];
__device__ __align__(16) __half g_W2l[N_SPECIES * HIDDEN * HIDDEN];
__device__ __align__(16) __half g_W3h[N_SPECIES * HIDDEN * HIDDEN];
__device__ __align__(16) __half g_W3l[N_SPECIES * HIDDEN * HIDDEN];
__device__ __align__(16) __half g_H1h[(size_t)N_ATOMS * HIDDEN];
__device__ __align__(16) __half g_H1l[(size_t)N_ATOMS * HIDDEN];
__device__ __align__(16) __half g_H2h[(size_t)N_ATOMS * HIDDEN];
__device__ __align__(16) __half g_H2l[(size_t)N_ATOMS * HIDDEN];
__device__ __align__(16) float  g_P[(size_t)NSPLIT * N_ATOMS * HIDDEN];

// ============================================================================
// Baseline-PTX primitives
// ============================================================================
__device__ __forceinline__ void cp16(uint32_t s, const void* g) {
    asm volatile("cp.async.cg.shared.global [%0], [%1], 16;\n" :: "r"(s), "l"(g));
}
__device__ __forceinline__ void cp_commit() {
    asm volatile("cp.async.commit_group;\n" ::: "memory");
}
template<int N> __device__ __forceinline__ void cp_wait() {
    asm volatile("cp.async.wait_group %0;\n" :: "n"(N) : "memory");
}
__device__ __forceinline__ void ldsm4(uint32_t& r0, uint32_t& r1, uint32_t& r2,
                                      uint32_t& r3, uint32_t a) {
    asm volatile("ldmatrix.sync.aligned.m8n8.x4.shared.b16 {%0,%1,%2,%3}, [%4];\n"
                 : "=r"(r0), "=r"(r1), "=r"(r2), "=r"(r3) : "r"(a));
}
__device__ __forceinline__ void mmaf16(float* c, const uint32_t* a, const uint32_t* b) {
    asm volatile(
        "mma.sync.aligned.m16n8k16.row.col.f32.f16.f16.f32 "
        "{%0,%1,%2,%3}, {%4,%5,%6,%7}, {%8,%9}, {%0,%1,%2,%3};\n"
        : "+f"(c[0]), "+f"(c[1]), "+f"(c[2]), "+f"(c[3])
        : "r"(a[0]), "r"(a[1]), "r"(a[2]), "r"(a[3]), "r"(b[0]), "r"(b[1]));
}
__device__ __forceinline__ uint32_t pkh(__half a, __half b) {
    __half2 t; t.x = a; t.y = b;
    return *(uint32_t*)&t;
}

// Fragment set for one k16 step (32x64 warp tile)
struct Frag {
    uint32_t ah[2][4], al[2][4];   // A: 2 m16 tiles, hi/lo planes
    uint32_t bh[8][2], bl[8][2];   // B: 8 n8 tiles (bl only for TERMS==3)
};

// ============================================================================
// Stage loaders (256 threads, KC=32)
// ============================================================================
// B plane: 128 rows x 64B = 512 cp16 -> 2/thread
template<int POFF>
__device__ __forceinline__ void cp_Bp(uint32_t st, const __half* B0, int ldb, int k0,
                                      int tid) {
#pragma unroll
    for (int i = 0; i < 2; ++i) {
        int j = tid + i * NTHREADS;
        int n = j >> 2, seg = j & 3;
        cp16(st + POFF + n * RST + seg * 16, B0 + (size_t)n * ldb + k0 + seg * 8);
    }
}
// A planes via cp (layers 2/3)
template<int POFF>
__device__ __forceinline__ void cp_Ap(uint32_t st, const __half* A0, int k0, int tid) {
#pragma unroll
    for (int i = 0; i < 2; ++i) {
        int j = tid + i * NTHREADS;
        int m = j >> 2, seg = j & 3;
        cp16(st + POFF + m * RST + seg * 16, A0 + (size_t)m * HIDDEN + k0 + seg * 8);
    }
}
// A fp32 (features): 128 rows x 32 f32 = 1024 float4 -> 4/thread
__device__ __forceinline__ void ldg_A(float4 av[4], const float* Abase, int k0, int tid,
                                      int Klim) {
#pragma unroll
    for (int i = 0; i < 4; ++i) {
        int j = tid + i * NTHREADS;
        int r = j >> 3, q = j & 7;
        int kg = k0 + q * 4;
        if (kg < Klim) av[i] = *(const float4*)(Abase + (size_t)r * N_FEAT + kg);
        else           av[i] = make_float4(0.f, 0.f, 0.f, 0.f);
    }
}
__device__ __forceinline__ void sts_A(const float4 av[4], char* sm, uint32_t stOff,
                                      int tid) {
#pragma unroll
    for (int i = 0; i < 4; ++i) {
        int j = tid + i * NTHREADS;
        int r = j >> 3, q = j & 7;
        float4 x = av[i];
        __half h0 = __float2half_rn(x.x), h1 = __float2half_rn(x.y);
        __half h2 = __float2half_rn(x.z), h3 = __float2half_rn(x.w);
        uint2 hp, lp;
        hp.x = pkh(h0, h1); hp.y = pkh(h2, h3);
        lp.x = pkh(__float2half_rn(x.x - __half2float(h0)),
                   __float2half_rn(x.y - __half2float(h1)));
        lp.y = pkh(__float2half_rn(x.z - __half2float(h2)),
                   __float2half_rn(x.w - __half2float(h3)));
        *(uint2*)(sm + stOff + SOFF_AH + r * RST + q * 8) = hp;
        *(uint2*)(sm + stOff + SOFF_AL + r * RST + q * 8) = lp;
    }
}

// ============================================================================
// Fragment load + MMA
// ============================================================================
template<int TERMS>
__device__ __forceinline__ void ldsm_step(uint32_t st, int ks, Frag& f,
                                          const uint32_t aOff[2], const uint32_t bOff[4]) {
#pragma unroll
    for (int mt = 0; mt < 2; ++mt) {
        ldsm4(f.ah[mt][0], f.ah[mt][1], f.ah[mt][2], f.ah[mt][3], st + aOff[mt] + ks * 32);
        ldsm4(f.al[mt][0], f.al[mt][1], f.al[mt][2], f.al[mt][3],
              st + aOff[mt] + PLANE + ks * 32);
    }
#pragma unroll
    for (int ng = 0; ng < 4; ++ng) {
        ldsm4(f.bh[2 * ng][0], f.bh[2 * ng][1], f.bh[2 * ng + 1][0], f.bh[2 * ng + 1][1],
              st + bOff[ng] + ks * 32);
        if (TERMS == 3)
            ldsm4(f.bl[2 * ng][0], f.bl[2 * ng][1], f.bl[2 * ng + 1][0],
                  f.bl[2 * ng + 1][1], st + bOff[ng] + PLANE + ks * 32);
    }
}
template<int TERMS>
__device__ __forceinline__ void mma_step(float acc[2][8][4], const Frag& f) {
#pragma unroll
    for (int mt = 0; mt < 2; ++mt)
#pragma unroll
        for (int nt = 0; nt < 8; ++nt) {
            mmaf16(acc[mt][nt], f.ah[mt], f.bh[nt]);
            mmaf16(acc[mt][nt], f.al[mt], f.bh[nt]);
            if (TERMS == 3) mmaf16(acc[mt][nt], f.ah[mt], f.bl[nt]);
        }
}

// ============================================================================
// Main GEMM.  D[m,n] = sum_k A[m,k]*B[n,k]
// ============================================================================
template<bool AFP32, int TERMS, bool SPLIT, int MINB>
__global__ void __launch_bounds__(NTHREADS, MINB)
gemm_main(const float* __restrict__ Afp,
          const __half* __restrict__ Ahg, const __half* __restrict__ Alg,
          int nchS, int nchTot,
          const __half* __restrict__ Bhg, const __half* __restrict__ Blg,
          int ldb,
          const float* __restrict__ bias,
          __half* __restrict__ Oh, __half* __restrict__ Ol,
          float* __restrict__ Pout)
{
    constexpr int BP = (TERMS == 2) ? 1 : 2;
    constexpr uint32_t SB_ = (uint32_t)(2 + BP) * PLANE;

    extern __shared__ char sm[];
    const uint32_t sb = (uint32_t)__cvta_generic_to_shared(sm);
    const int tid = threadIdx.x;
    const int nblk = blockIdx.x;
    const int row0 = blockIdx.y * MT;
    const int s = row0 >> 13;
    const int z = SPLIT ? blockIdx.z : 0;
    const int kbase = z * nchS * KC;
    const int nch = SPLIT ? min(nchS, nchTot - z * nchS) : nchS;
    const int Klim = AFP32 ? (N_FEAT - kbase) : 0x7fffffff;

    const __half* Bh0 = Bhg + ((size_t)s * HIDDEN + nblk * NTILE) * ldb + kbase;
    const __half* Bl0 = (TERMS == 3)
        ? Blg + ((size_t)s * HIDDEN + nblk * NTILE) * ldb + kbase : nullptr;
    const float* Abase = AFP32 ? (Afp + (size_t)row0 * N_FEAT + kbase) : nullptr;
    const __half* Ah0 = AFP32 ? nullptr : (Ahg + (size_t)row0 * HIDDEN);
    const __half* Al0 = AFP32 ? nullptr : (Alg + (size_t)row0 * HIDDEN);

    float* sbias = (float*)(sm + NSTAGE * SB_);
    if (!SPLIT && tid < NTILE) sbias[tid] = bias[s * HIDDEN + nblk * NTILE + tid];

    // ---- prologue: stages 0,1 filled; av <- chunk 2 ----
    float4 av[4];
    if (AFP32) {
        ldg_A(av, Abase, 0, tid, Klim);
        sts_A(av, sm, 0, tid);
    } else {
        cp_Ap<SOFF_AH>(sb, Ah0, 0, tid);
        cp_Ap<SOFF_AL>(sb, Al0, 0, tid);
    }
    cp_Bp<SOFF_BH>(sb, Bh0, ldb, 0, tid);
    if (TERMS == 3) cp_Bp<SOFF_BL>(sb, Bl0, ldb, 0, tid);
    cp_commit();
    if (AFP32) {
        ldg_A(av, Abase, KC, tid, Klim);
        sts_A(av, sm, SB_, tid);
    } else {
        cp_Ap<SOFF_AH>(sb + SB_, Ah0, KC, tid);
        cp_Ap<SOFF_AL>(sb + SB_, Al0, KC, tid);
    }
    cp_Bp<SOFF_BH>(sb + SB_, Bh0, ldb, KC, tid);
    if (TERMS == 3) cp_Bp<SOFF_BL>(sb + SB_, Bl0, ldb, KC, tid);
    cp_commit();
    if (AFP32 && nch > 2) ldg_A(av, Abase, 2 * KC, tid, Klim);

    // ---- per-warp fragment addressing: 8 warps, 32x64 tiles (4M x 2N) ----
    const int lane = tid & 31, wid = tid >> 5;
    const int m0 = (wid & 3) * 32, n0 = (wid >> 2) * 64;
    const int lr = lane & 15, lcb = (lane >> 4) * 16;
    uint32_t aOff[2], bOff[4];
#pragma unroll
    for (int mt = 0; mt < 2; ++mt)
        aOff[mt] = SOFF_AH + (uint32_t)(m0 + mt * 16 + lr) * RST + lcb;
    const int brow = (lane & 7) + ((lane & 16) >> 1);
    const int bcb = (lane & 8) * 2;
#pragma unroll
    for (int ng = 0; ng < 4; ++ng)
        bOff[ng] = SOFF_BH + (uint32_t)(n0 + ng * 16 + brow) * RST + bcb;

    float acc[2][8][4];
#pragma unroll
    for (int mt = 0; mt < 2; ++mt)
#pragma unroll
        for (int nt = 0; nt < 8; ++nt)
#pragma unroll
            for (int q = 0; q < 4; ++q) acc[mt][nt][q] = 0.f;

    // ---- main loop: 3-stage ring, 2-ahead prefetch, 2 k-steps per chunk ----
    Frag f;
    int stc = 0, st2 = 2;  // stage index of chunk c and c+2 (mod 3)
    for (int c = 0; c < nch; ++c) {
        if (c + 1 < nch) { cp_wait<1>(); } else { cp_wait<0>(); }
        __syncthreads();
        const uint32_t cur = sb + (uint32_t)stc * SB_;
        const uint32_t nx2 = sb + (uint32_t)st2 * SB_;
        const bool pf = (c + 2 < nch);
        const int k2 = (c + 2) * KC;

        // ks0: + A split-store for chunk c+2
        ldsm_step<TERMS>(cur, 0, f, aOff, bOff);
        if (AFP32 && pf) sts_A(av, sm, (uint32_t)st2 * SB_, tid);
        mma_step<TERMS>(acc, f);

        // ks1: + cp for chunk c+2, ldg A for chunk c+3
        ldsm_step<TERMS>(cur, 1, f, aOff, bOff);
        if (pf) {
            cp_Bp<SOFF_BH>(nx2, Bh0, ldb, k2, tid);
            if (TERMS == 3) cp_Bp<SOFF_BL>(nx2, Bl0, ldb, k2, tid);
            if (!AFP32) {
                cp_Ap<SOFF_AH>(nx2, Ah0, k2, tid);
                cp_Ap<SOFF_AL>(nx2, Al0, k2, tid);
            }
            cp_commit();
        }
        if (AFP32 && c + 3 < nch) ldg_A(av, Abase, (c + 3) * KC, tid, Klim);
        mma_step<TERMS>(acc, f);

        stc = (stc == 2) ? 0 : stc + 1;
        st2 = (st2 == 2) ? 0 : st2 + 1;
    }

    // ---- epilogue ----
    if (SPLIT) {
        float* P = Pout + (size_t)z * N_ATOMS * HIDDEN;
#pragma unroll
        for (int mt = 0; mt < 2; ++mt)
#pragma unroll
            for (int nt = 0; nt < 8; ++nt) {
                const int rg = row0 + m0 + mt * 16 + (lane >> 2);
                const int cg = nblk * NTILE + n0 + nt * 8 + (lane & 3) * 2;
                *(float2*)(P + (size_t)rg * HIDDEN + cg) =
                    make_float2(acc[mt][nt][0], acc[mt][nt][1]);
                *(float2*)(P + (size_t)(rg + 8) * HIDDEN + cg) =
                    make_float2(acc[mt][nt][2], acc[mt][nt][3]);
            }
    } else {
#pragma unroll
        for (int mt = 0; mt < 2; ++mt)
#pragma unroll
            for (int nt = 0; nt < 8; ++nt) {
                const int rg = row0 + m0 + mt * 16 + (lane >> 2);
                const int cl = n0 + nt * 8 + (lane & 3) * 2;
                const int cg = nblk * NTILE + cl;
                const float b0 = sbias[cl], b1 = sbias[cl + 1];
                float v[4];
                v[0] = acc[mt][nt][0] + b0; v[1] = acc[mt][nt][1] + b1;
                v[2] = acc[mt][nt][2] + b0; v[3] = acc[mt][nt][3] + b1;
#pragma unroll
                for (int q = 0; q < 4; ++q) v[q] = v[q] / (1.f + __expf(-v[q]));
                __half h0 = __float2half_rn(v[0]), h1 = __float2half_rn(v[1]);
                __half h2 = __float2half_rn(v[2]), h3 = __float2half_rn(v[3]);
                uint32_t hi0 = pkh(h0, h1), hi1 = pkh(h2, h3);
                uint32_t lo0 = pkh(__float2half_rn(v[0] - __half2float(h0)),
                                   __float2half_rn(v[1] - __half2float(h1)));
                uint32_t lo1 = pkh(__float2half_rn(v[2] - __half2float(h2)),
                                   __float2half_rn(v[3] - __half2float(h3)));
                *(uint32_t*)(Oh + (size_t)rg * HIDDEN + cg) = hi0;
                *(uint32_t*)(Ol + (size_t)rg * HIDDEN + cg) = lo0;
                *(uint32_t*)(Oh + (size_t)(rg + 8) * HIDDEN + cg) = hi1;
                *(uint32_t*)(Ol + (size_t)(rg + 8) * HIDDEN + cg) = lo1;
            }
    }
}

// ============================================================================
// Split-K combine: sum 4 partials + bias -> silu -> fp16 hi/lo planes
// ============================================================================
__global__ void __launch_bounds__(256)
combine_silu(const float* __restrict__ P, const float* __restrict__ bias,
             __half* __restrict__ Oh, __half* __restrict__ Ol)
{
    const size_t i4 = ((size_t)blockIdx.x * 256 + threadIdx.x) * 4;
    const int row = (int)(i4 >> 8);
    const int col = (int)(i4 & 255);
    const int s = row >> 13;
    float4 a0 = *(const float4*)(P + i4);
    float4 a1 = *(const float4*)(P + (size_t)N_ATOMS * HIDDEN + i4);
    float4 a2 = *(const float4*)(P + (size_t)2 * N_ATOMS * HIDDEN + i4);
    float4 a3 = *(const float4*)(P + (size_t)3 * N_ATOMS * HIDDEN + i4);
    const float* bp = bias + s * HIDDEN + col;
    float v[4] = {(a0.x + a1.x) + (a2.x + a3.x) + bp[0],
                  (a0.y + a1.y) + (a2.y + a3.y) + bp[1],
                  (a0.z + a1.z) + (a2.z + a3.z) + bp[2],
                  (a0.w + a1.w) + (a2.w + a3.w) + bp[3]};
#pragma unroll
    for (int q = 0; q < 4; ++q) v[q] = v[q] / (1.f + __expf(-v[q]));
    __half h0 = __float2half_rn(v[0]), h1 = __float2half_rn(v[1]);
    __half h2 = __float2half_rn(v[2]), h3 = __float2half_rn(v[3]);
    uint2 hp, lp;
    hp.x = pkh(h0, h1); hp.y = pkh(h2, h3);
    lp.x = pkh(__float2half_rn(v[0] - __half2float(h0)),
               __float2half_rn(v[1] - __half2float(h1)));
    lp.y = pkh(__float2half_rn(v[2] - __half2float(h2)),
               __float2half_rn(v[3] - __half2float(h3)));
    *(uint2*)(Oh + i4) = hp;
    *(uint2*)(Ol + i4) = lp;
}

// ============================================================================
// Weight transpose + fp16 hi/lo split:  W[s][f][h] -> Wt[s][h][f]
// ============================================================================
__global__ void transpose_split(const float* __restrict__ W,
                                __half* __restrict__ Th,
                                __half* __restrict__ Tl,
                                int F, int H)
{
    __shared__ float t[32][33];
    const int s = blockIdx.z;
    const int f0 = blockIdx.x * 32, h0 = blockIdx.y * 32;
    const float* Ws = W + (size_t)s * F * H;
#pragma unroll
    for (int i = threadIdx.y; i < 32; i += 8) {
        int f = f0 + i, h = h0 + threadIdx.x;
        t[i][threadIdx.x] = (f < F) ? Ws[(size_t)f * H + h] : 0.f;
    }
    __syncthreads();
    __half* Ths = Th + (size_t)s * H * F;
    __half* Tls = Tl ? (Tl + (size_t)s * H * F) : nullptr;
#pragma unroll
    for (int i = threadIdx.y; i < 32; i += 8) {
        int h = h0 + i, f = f0 + threadIdx.x;
        if (f >= F) continue;
        float v = t[threadIdx.x][i];
        __half hi = __float2half_rn(v);
        Ths[(size_t)h * F + f] = hi;
        if (Tls) Tls[(size_t)h * F + f] = __float2half_rn(v - __half2float(hi));
    }
}

// ============================================================================
// Output zero + final layer-4 dot + segment scatter-add
// ============================================================================
__global__ void zero_out(float* out, int n) {
    int i = blockIdx.x * blockDim.x + threadIdx.x;
    if (i < n) out[i] = 0.f;
}

__global__ void __launch_bounds__(256)
layer4_reduce(const __half* __restrict__ Hh, const __half* __restrict__ Hl,
              const float* __restrict__ W4, const float* __restrict__ b4,
              const int* __restrict__ sidx, float* __restrict__ out)
{
    __shared__ float w[HIDDEN];
    const int atom = blockIdx.x * 256 + threadIdx.x;
    const int s = atom >> 13;
    w[threadIdx.x] = W4[s * HIDDEN + threadIdx.x];
    __syncthreads();

    const uint4* ph = (const uint4*)(Hh + (size_t)atom * HIDDEN);
    const uint4* pl = (const uint4*)(Hl + (size_t)atom * HIDDEN);
    float e = b4[s];
#pragma unroll 8
    for (int i = 0; i < 32; ++i) {
        uint4 a = ph[i];
        uint4 c = pl[i];
        const uint32_t* ap = &a.x;
        const uint32_t* cp = &c.x;
#pragma unroll
        for (int j = 0; j < 4; ++j) {
            float2 hv = __half22float2(*(__half2*)&ap[j]);
            float2 lv = __half22float2(*(__half2*)&cp[j]);
            int col = i * 8 + j * 2;
            e += (hv.x + lv.x) * w[col];
            e += (hv.y + lv.y) * w[col + 1];
        }
    }
    atomicAdd(out + sidx[atom], e);
}

// ============================================================================
// Host launcher
// ============================================================================
extern "C" void kernel_launch(void* const* d_in, const int* in_sizes, int n_in,
                              void* d_out, int out_size)
{
    int o = 0;
    const float* feat = (const float*)d_in[o++];
    const int* sidx = (const int*)d_in[o++];
    if (o < n_in && in_sizes[o] == 1) o++;  // n_structures scalar, if present
    const float* W1 = (const float*)d_in[o++];
    const float* b1 = (const float*)d_in[o++];
    const float* W2 = (const float*)d_in[o++];
    const float* b2 = (const float*)d_in[o++];
    const float* W3 = (const float*)d_in[o++];
    const float* b3 = (const float*)d_in[o++];
    const float* W4 = (const float*)d_in[o++];
    const float* b4 = (const float*)d_in[o++];

    __half *w1h, *w2h, *w2l, *w3h, *w3l, *h1h, *h1l, *h2h, *h2l;
    float* pbuf;
    cudaGetSymbolAddress((void**)&w1h, g_W1h);
    cudaGetSymbolAddress((void**)&w2h, g_W2h);
    cudaGetSymbolAddress((void**)&w2l, g_W2l);
    cudaGetSymbolAddress((void**)&w3h, g_W3h);
    cudaGetSymbolAddress((void**)&w3l, g_W3l);
    cudaGetSymbolAddress((void**)&h1h, g_H1h);
    cudaGetSymbolAddress((void**)&h1l, g_H1l);
    cudaGetSymbolAddress((void**)&h2h, g_H2h);
    cudaGetSymbolAddress((void**)&h2l, g_H2l);
    cudaGetSymbolAddress((void**)&pbuf, g_P);

    const int SMEM1 = NSTAGE * 3 * PLANE;            // 92160 (2-term, B 1 plane)
    const int SMEM23 = NSTAGE * 4 * PLANE + 512;     // 123392 (3-term)
    cudaFuncSetAttribute((const void*)gemm_main<true, 2, true, 2>,
                         cudaFuncAttributeMaxDynamicSharedMemorySize, SMEM1);
    cudaFuncSetAttribute((const void*)gemm_main<false, 3, false, 1>,
                         cudaFuncAttributeMaxDynamicSharedMemorySize, SMEM23);

    // Prep: transpose (+ split for W2/W3) to K-major fp16 planes
    transpose_split<<<dim3(N_FEAT / 32, HIDDEN / 32, N_SPECIES), dim3(32, 8)>>>(
        W1, w1h, nullptr, N_FEAT, HIDDEN);
    transpose_split<<<dim3(HIDDEN / 32, HIDDEN / 32, N_SPECIES), dim3(32, 8)>>>(
        W2, w2h, w2l, HIDDEN, HIDDEN);
    transpose_split<<<dim3(HIDDEN / 32, HIDDEN / 32, N_SPECIES), dim3(32, 8)>>>(
        W3, w3h, w3l, HIDDEN, HIDDEN);

    // Layer 1: fp16 2-term, split-K x4 -> fp32 partials -> combine
    gemm_main<true, 2, true, 2>
        <<<dim3(HIDDEN / NTILE, N_ATOMS / MT, NSPLIT), NTHREADS, SMEM1>>>(
        feat, nullptr, nullptr, NCHS, TOTCH,
        w1h, nullptr, N_FEAT, nullptr, nullptr, nullptr, pbuf);
    combine_silu<<<(N_ATOMS * HIDDEN) / (256 * 4), 256>>>(pbuf, b1, h1h, h1l);

    const dim3 grid2(HIDDEN / NTILE, N_ATOMS / MT);

    // Layer 2: fp16 3-term (K = 256, 8 chunks)
    gemm_main<false, 3, false, 1><<<grid2, NTHREADS, SMEM23>>>(
        nullptr, h1h, h1l, HIDDEN / KC, HIDDEN / KC,
        w2h, w2l, HIDDEN, b2, h2h, h2l, nullptr);

    // Layer 3
    gemm_main<false, 3, false, 1><<<grid2, NTHREADS, SMEM23>>>(
        nullptr, h2h, h2l, HIDDEN / KC, HIDDEN / KC,
        w3h, w3l, HIDDEN, b3, h1h, h1l, nullptr);

    // Layer 4 + segment sum
    zero_out<<<(out_size + 255) / 256, 256>>>((float*)d_out, out_size);
    layer4_reduce<<<N_ATOMS / 256, 256>>>(h1h, h1l, W4, b4, sidx, (float*)d_out);
}